// round 6
// baseline (speedup 1.0000x reference)
#include <cuda_runtime.h>
#include <cuda_bf16.h>
#include <math.h>
#include <stdint.h>

// Problem constants
#define CB   4096     // batch B
#define CDIN 1024     // D_IN
#define CD   256      // D
#define CK   1024     // K clusters
#define CL   32768    // L queue_n rows
#define CKQ  4096     // K*Q_MULT queue_k rows
#define PS_N 32       // j-splits, LSE over queue_n
#define PP_N (PS_N*2)
#define PS_K 16       // j-splits, LSE over queue_k
#define PP_K (PS_K*2)
#define INV_TEMP (1.0f/0.07f)

// ------------------------- scratch (__device__ globals; no runtime alloc) -------------------------
static __device__ __align__(16) float g_F1[CB*CD];
static __device__ __align__(16) float g_L[CB*CK];
static __device__ __align__(16) float g_L2[CB*CK];
static __device__ __align__(16) float g_aggk1[CK*CD];
static __device__ __align__(16) float g_Cpart[8*CB*CD];   // partitioned split-K partials
static __device__ float g_norm1[CK];
static __device__ float g_norm2[CK];
static __device__ float g_lposN[CB];
static __device__ float g_lposK[CK];
static __device__ float g_pmN[CB*PP_N];
static __device__ float g_psN[CB*PP_N];
static __device__ float g_pmK[CK*PP_K];
static __device__ float g_psK[CK*PP_K];
// split-bf16 operand buffers (hi/lo pairs) -- separate per parallel branch
static __device__ __align__(16) __nv_bfloat16 g_xh[CB*CDIN],  g_xl[CB*CDIN];
static __device__ __align__(16) __nv_bfloat16 g_x2h[CB*CDIN], g_x2l[CB*CDIN];
static __device__ __align__(16) __nv_bfloat16 g_wth[CD*CDIN], g_wtl[CD*CDIN];
static __device__ __align__(16) __nv_bfloat16 g_wt2h[CD*CDIN],g_wt2l[CD*CDIN];
static __device__ __align__(16) __nv_bfloat16 g_F1h[CB*CD],  g_F1l[CB*CD];
static __device__ __align__(16) __nv_bfloat16 g_F2h[CB*CD],  g_F2l[CB*CD];
static __device__ __align__(16) __nv_bfloat16 g_ctx1h[CK*CD], g_ctx1l[CK*CD];
static __device__ __align__(16) __nv_bfloat16 g_ctx2h[CK*CD], g_ctx2l[CK*CD];
static __device__ __align__(16) __nv_bfloat16 g_LTh[CK*CB],  g_LTl[CK*CB];
static __device__ __align__(16) __nv_bfloat16 g_LT2h[CK*CB], g_LT2l[CK*CB];
static __device__ __align__(16) __nv_bfloat16 g_FTh[CD*CB],  g_FTl[CD*CB];
static __device__ __align__(16) __nv_bfloat16 g_FT2h[CD*CB], g_FT2l[CD*CB];
static __device__ __align__(16) __nv_bfloat16 g_aggk1b[CK*CD];
static __device__ __align__(16) __nv_bfloat16 g_qnb[CL*CD];
static __device__ __align__(16) __nv_bfloat16 g_qkb[CKQ*CD];

// ------------------------- PTX helpers (sm_80-era only: compute_103 virtual arch!) -------------------------
__device__ __forceinline__ uint32_t smem_u32(const void* p) {
    uint32_t a;
    asm("{ .reg .u64 t; cvta.to.shared.u64 t, %1; cvt.u32.u64 %0, t; }" : "=r"(a) : "l"(p));
    return a;
}
__device__ __forceinline__ void cp16(uint32_t dst, const void* src) {
    asm volatile("cp.async.cg.shared.global [%0], [%1], 16;" :: "r"(dst), "l"(src));
}
#define CP_COMMIT() asm volatile("cp.async.commit_group;" ::: "memory")
#define CP_WAIT0()  asm volatile("cp.async.wait_group 0;" ::: "memory")

__device__ __forceinline__ void ldm_x4(uint32_t r[4], uint32_t addr) {
    asm volatile("ldmatrix.sync.aligned.m8n8.x4.shared.b16 {%0,%1,%2,%3}, [%4];"
                 : "=r"(r[0]), "=r"(r[1]), "=r"(r[2]), "=r"(r[3]) : "r"(addr));
}
__device__ __forceinline__ void mma_bf16(float c[4], const uint32_t a[4], uint32_t b0, uint32_t b1) {
    asm volatile("mma.sync.aligned.m16n8k16.row.col.f32.bf16.bf16.f32 "
                 "{%0,%1,%2,%3}, {%4,%5,%6,%7}, {%8,%9}, {%0,%1,%2,%3};"
                 : "+f"(c[0]), "+f"(c[1]), "+f"(c[2]), "+f"(c[3])
                 : "r"(a[0]), "r"(a[1]), "r"(a[2]), "r"(a[3]), "r"(b0), "r"(b1));
}

__device__ __forceinline__ float gumbelf(float u) {
    u = u * (1.0f - 2e-6f) + 1e-6f;
    return -logf(-logf(u));
}
__device__ __forceinline__ void split2(float v, __nv_bfloat16& h, __nv_bfloat16& l) {
    h = __float2bfloat16_rn(v);
    l = __float2bfloat16_rn(v - __bfloat162float(h));
}

// ------------------------- elementwise split / transpose-split -------------------------
__global__ void k_split(const float* __restrict__ in, __nv_bfloat16* __restrict__ hi,
                        __nv_bfloat16* __restrict__ lo) {
    int i = blockIdx.x*256 + threadIdx.x;
    float4 v = reinterpret_cast<const float4*>(in)[i];
    __nv_bfloat16 h[4], l[4];
    split2(v.x, h[0], l[0]); split2(v.y, h[1], l[1]);
    split2(v.z, h[2], l[2]); split2(v.w, h[3], l[3]);
    reinterpret_cast<uint2*>(hi)[i] = *reinterpret_cast<uint2*>(h);
    reinterpret_cast<uint2*>(lo)[i] = *reinterpret_cast<uint2*>(l);
}

// in [R,C] fp32 -> out hi/lo bf16 [C,R]
__global__ void k_tsplit(const float* __restrict__ in, __nv_bfloat16* __restrict__ hiT,
                         __nv_bfloat16* __restrict__ loT, int R, int C) {
    __shared__ float t[32][33];
    int c0 = blockIdx.x*32, r0 = blockIdx.y*32;
    int tx = threadIdx.x, ty = threadIdx.y;  // 32 x 8
    #pragma unroll
    for (int i = 0; i < 4; i++)
        t[ty + i*8][tx] = in[(size_t)(r0 + ty + i*8)*C + c0 + tx];
    __syncthreads();
    #pragma unroll
    for (int i = 0; i < 4; i++) {
        float v = t[tx][ty + i*8];
        __nv_bfloat16 h, l;
        split2(v, h, l);
        size_t o = (size_t)(c0 + ty + i*8)*R + r0 + tx;
        hiT[o] = h; loT[o] = l;
    }
}

// ------------------------- row l2norm (D=256) with fused split-K partial reduce -------------------------
// in = base of ks stacked partials of mn floats each (ks=1: plain input). Optional divisor (+EPS).
__global__ void k_l2norm(const float* __restrict__ in, int ks, int mn4,
                         float* __restrict__ outf,
                         __nv_bfloat16* __restrict__ outhi, __nv_bfloat16* __restrict__ outlo,
                         const float* __restrict__ divisor) {
    int r = blockIdx.x, t = threadIdx.x;  // 64 threads
    __shared__ float sh[2];
    int idx = r*64 + t;
    const float4* p = reinterpret_cast<const float4*>(in);
    float4 v = p[idx];
    for (int z = 1; z < ks; z++) {
        float4 w = p[(size_t)z*mn4 + idx];
        v.x += w.x; v.y += w.y; v.z += w.z; v.w += w.w;
    }
    if (divisor) {
        float d = 1.0f / (divisor[r] + 1e-8f);
        v.x *= d; v.y *= d; v.z *= d; v.w *= d;
    }
    float ss = v.x*v.x + v.y*v.y + v.z*v.z + v.w*v.w;
    #pragma unroll
    for (int o = 16; o; o >>= 1) ss += __shfl_xor_sync(0xffffffffu, ss, o);
    if ((t & 31) == 0) sh[t >> 5] = ss;
    __syncthreads();
    float s = rsqrtf(fmaxf(sh[0] + sh[1], 1e-12f));
    v.x *= s; v.y *= s; v.z *= s; v.w *= s;
    if (outf) reinterpret_cast<float4*>(outf)[idx] = v;
    if (outhi) {
        __nv_bfloat16 h[4], l[4];
        split2(v.x, h[0], l[0]); split2(v.y, h[1], l[1]);
        split2(v.z, h[2], l[2]); split2(v.w, h[3], l[3]);
        reinterpret_cast<uint2*>(outhi)[idx] = *reinterpret_cast<uint2*>(h);
        if (outlo) reinterpret_cast<uint2*>(outlo)[idx] = *reinterpret_cast<uint2*>(l);
    }
}

// queue = l2norm(2*l2norm(queue_k) + qnoise), fused; plain bf16 output
__global__ void k_queue_combine(const float* __restrict__ qk, const float* __restrict__ noise,
                                __nv_bfloat16* __restrict__ outb) {
    int r = blockIdx.x, t = threadIdx.x;  // 64 threads
    __shared__ float sh[2];
    float4 v = reinterpret_cast<const float4*>(qk)[r*64 + t];
    float ss = v.x*v.x + v.y*v.y + v.z*v.z + v.w*v.w;
    #pragma unroll
    for (int o = 16; o; o >>= 1) ss += __shfl_xor_sync(0xffffffffu, ss, o);
    if ((t & 31) == 0) sh[t >> 5] = ss;
    __syncthreads();
    float s1 = 2.0f * rsqrtf(fmaxf(sh[0] + sh[1], 1e-12f));
    float4 n = reinterpret_cast<const float4*>(noise)[r*64 + t];
    float4 w = make_float4(v.x*s1 + n.x, v.y*s1 + n.y, v.z*s1 + n.z, v.w*s1 + n.w);
    __syncthreads();
    float ss2 = w.x*w.x + w.y*w.y + w.z*w.z + w.w*w.w;
    #pragma unroll
    for (int o = 16; o; o >>= 1) ss2 += __shfl_xor_sync(0xffffffffu, ss2, o);
    if ((t & 31) == 0) sh[t >> 5] = ss2;
    __syncthreads();
    float s2 = rsqrtf(fmaxf(sh[0] + sh[1], 1e-12f));
    w.x *= s2; w.y *= s2; w.z *= s2; w.w *= s2;
    __nv_bfloat162 lo2 = __floats2bfloat162_rn(w.x, w.y);
    __nv_bfloat162 hi2 = __floats2bfloat162_rn(w.z, w.w);
    uint2 u = make_uint2(*(uint32_t*)&lo2, *(uint32_t*)&hi2);
    reinterpret_cast<uint2*>(outb)[r*64 + t] = u;
}

// ------------------------- split-bf16 NT GEMM (validated R5) -------------------------
#define GT_RS    144u
#define GT_TILE  (128u*GT_RS)
#define GT_STAGE (4u*GT_TILE)
#define GT_SMEM  (2u*GT_STAGE)

__device__ __forceinline__ void gt_load(uint32_t dst, const __nv_bfloat16* src,
                                        int row0, int K, int kc) {
    int tid = threadIdx.x;
    #pragma unroll
    for (int i = 0; i < 4; i++) {
        int idx = tid + (i << 8);
        int row = idx >> 3;
        int cc = (idx & 7) << 3;
        cp16(dst + (uint32_t)row*GT_RS + (uint32_t)cc*2u,
             src + (size_t)(row0 + row)*K + kc + cc);
    }
}

__global__ void __launch_bounds__(256, 1) k_mma3(
    const __nv_bfloat16* __restrict__ Ah, const __nv_bfloat16* __restrict__ Al,
    const __nv_bfloat16* __restrict__ Bh, const __nv_bfloat16* __restrict__ Bl,
    float* __restrict__ C, int M, int N, int K, int ksplit)
{
    extern __shared__ char sm[];
    uint32_t base = (smem_u32(sm) + 127u) & ~127u;
    int tid = threadIdx.x, lane = tid & 31, w = tid >> 5;
    int mg = w & 3, ng = w >> 2;
    int m0 = blockIdx.x * 128, n0 = blockIdx.y * 128;
    int Klocal = K / ksplit, kbase = blockIdx.z * Klocal;
    float* out = C + (size_t)blockIdx.z * M * N;
    int lt = lane >> 3, lr = lane & 7;
    uint32_t aOff = (uint32_t)(mg*32 + (lt & 1)*8 + lr)*GT_RS + (uint32_t)((lt >> 1)*8)*2u;
    uint32_t bOff = (uint32_t)(ng*64 + (lt >> 1)*8 + lr)*GT_RS + (uint32_t)((lt & 1)*8)*2u;

    {
        uint32_t s0 = base;
        gt_load(s0 + 0u*GT_TILE, Ah, m0, K, kbase);
        gt_load(s0 + 1u*GT_TILE, Al, m0, K, kbase);
        gt_load(s0 + 2u*GT_TILE, Bh, n0, K, kbase);
        gt_load(s0 + 3u*GT_TILE, Bl, n0, K, kbase);
        CP_COMMIT();
    }

    float acc[2][8][4];
    #pragma unroll
    for (int mt = 0; mt < 2; mt++)
        #pragma unroll
        for (int nt = 0; nt < 8; nt++)
            #pragma unroll
            for (int c = 0; c < 4; c++) acc[mt][nt][c] = 0.0f;

    int nk = Klocal >> 6;
    for (int kc = 0; kc < nk; kc++) {
        CP_WAIT0();
        __syncthreads();
        if (kc + 1 < nk) {
            uint32_t sn = base + (uint32_t)((kc + 1) & 1)*GT_STAGE;
            int kn = kbase + (kc + 1)*64;
            gt_load(sn + 0u*GT_TILE, Ah, m0, K, kn);
            gt_load(sn + 1u*GT_TILE, Al, m0, K, kn);
            gt_load(sn + 2u*GT_TILE, Bh, n0, K, kn);
            gt_load(sn + 3u*GT_TILE, Bl, n0, K, kn);
            CP_COMMIT();
        }
        uint32_t st = base + (uint32_t)(kc & 1)*GT_STAGE;
        #pragma unroll
        for (int k0 = 0; k0 < 64; k0 += 16) {
            uint32_t a0h[4], a1h[4], a0l[4], a1l[4];
            ldm_x4(a0h, st + 0u*GT_TILE + aOff + (uint32_t)k0*2u);
            ldm_x4(a1h, st + 0u*GT_TILE + aOff + 16u*GT_RS + (uint32_t)k0*2u);
            ldm_x4(a0l, st + 1u*GT_TILE + aOff + (uint32_t)k0*2u);
            ldm_x4(a1l, st + 1u*GT_TILE + aOff + 16u*GT_RS + (uint32_t)k0*2u);
            #pragma unroll
            for (int np = 0; np < 4; np++) {
                uint32_t bh[4], bl[4];
                ldm_x4(bh, st + 2u*GT_TILE + bOff + (uint32_t)np*16u*GT_RS + (uint32_t)k0*2u);
                ldm_x4(bl, st + 3u*GT_TILE + bOff + (uint32_t)np*16u*GT_RS + (uint32_t)k0*2u);
                mma_bf16(acc[0][2*np+0], a0h, bh[0], bh[1]);
                mma_bf16(acc[0][2*np+1], a0h, bh[2], bh[3]);
                mma_bf16(acc[1][2*np+0], a1h, bh[0], bh[1]);
                mma_bf16(acc[1][2*np+1], a1h, bh[2], bh[3]);
                mma_bf16(acc[0][2*np+0], a0h, bl[0], bl[1]);
                mma_bf16(acc[0][2*np+1], a0h, bl[2], bl[3]);
                mma_bf16(acc[1][2*np+0], a1h, bl[0], bl[1]);
                mma_bf16(acc[1][2*np+1], a1h, bl[2], bl[3]);
                mma_bf16(acc[0][2*np+0], a0l, bh[0], bh[1]);
                mma_bf16(acc[0][2*np+1], a0l, bh[2], bh[3]);
                mma_bf16(acc[1][2*np+0], a1l, bh[0], bh[1]);
                mma_bf16(acc[1][2*np+1], a1l, bh[2], bh[3]);
            }
        }
    }

    int gid = lane >> 2, qc = (lane & 3) << 1;
    #pragma unroll
    for (int mt = 0; mt < 2; mt++) {
        #pragma unroll
        for (int nt = 0; nt < 8; nt++) {
            int r0 = m0 + mg*32 + mt*16 + gid;
            int c0 = n0 + ng*64 + nt*8 + qc;
            float2 v0 = make_float2(acc[mt][nt][0], acc[mt][nt][1]);
            float2 v1 = make_float2(acc[mt][nt][2], acc[mt][nt][3]);
            *reinterpret_cast<float2*>(&out[(size_t)r0*N + c0]) = v0;
            *reinterpret_cast<float2*>(&out[(size_t)(r0 + 8)*N + c0]) = v1;
        }
    }
}

// ------------------------- HMMA bf16 LSE (validated R4) -------------------------
#define RSB 528u
#define LSE_TILE_BYTES (128u*RSB)
#define LSE_SMEM (3u*LSE_TILE_BYTES + 128u)

__device__ __forceinline__ void lse_load_tile(uint32_t dstbase, const __nv_bfloat16* src) {
    int tid = threadIdx.x;
    #pragma unroll
    for (int i = 0; i < 16; i++) {
        int idx = tid + (i << 8);
        int row = idx >> 5;
        int c = idx & 31;
        cp16(dstbase + (uint32_t)row*RSB + (uint32_t)c*16u, src + row*256 + c*8);
    }
}

__global__ void __launch_bounds__(256, 1) k_lse_mma(
    const __nv_bfloat16* __restrict__ A, const __nv_bfloat16* __restrict__ Q,
    float* __restrict__ pm, float* __restrict__ ps, int jspan, int ppart, float scale)
{
    extern __shared__ char smem_raw[];
    uint32_t base = (smem_u32(smem_raw) + 127u) & ~127u;
    uint32_t aBase  = base;
    uint32_t qBase0 = base + LSE_TILE_BYTES;
    uint32_t qBase1 = base + 2u*LSE_TILE_BYTES;

    int tid = threadIdx.x;
    int lane = tid & 31, w = tid >> 5;
    int mg = w & 3;
    int ng = w >> 2;
    int m0 = blockIdx.x * 128;
    int jbase = blockIdx.y * jspan;
    int nj = jspan >> 7;

    int lt = lane >> 3, lr = lane & 7;
    uint32_t aAddr = aBase + (uint32_t)(mg*32 + (lt & 1)*8 + lr)*RSB + (uint32_t)((lt >> 1)*8)*2u;
    uint32_t qOff = (uint32_t)(ng*64 + (lt >> 1)*8 + lr)*RSB + (uint32_t)((lt & 1)*8)*2u;

    lse_load_tile(aBase, A + (size_t)m0*256);
    lse_load_tile(qBase0, Q + (size_t)jbase*256);
    CP_COMMIT();

    float mrun[4], srun[4];
    #pragma unroll
    for (int s = 0; s < 4; s++) { mrun[s] = -INFINITY; srun[s] = 0.0f; }

    for (int jt = 0; jt < nj; jt++) {
        CP_WAIT0();
        __syncthreads();
        if (jt + 1 < nj) {
            lse_load_tile((jt & 1) ? qBase0 : qBase1, Q + (size_t)(jbase + (jt+1)*128)*256);
            CP_COMMIT();
        }
        uint32_t qB = (jt & 1) ? qBase1 : qBase0;

        float acc[2][8][4];
        #pragma unroll
        for (int mt = 0; mt < 2; mt++)
            #pragma unroll
            for (int nt = 0; nt < 8; nt++)
                #pragma unroll
                for (int c = 0; c < 4; c++) acc[mt][nt][c] = 0.0f;

        #pragma unroll 4
        for (int k0 = 0; k0 < 256; k0 += 16) {
            uint32_t a0[4], a1[4];
            ldm_x4(a0, aAddr + (uint32_t)k0*2u);
            ldm_x4(a1, aAddr + 16u*RSB + (uint32_t)k0*2u);
            #pragma unroll
            for (int np = 0; np < 4; np++) {
                uint32_t b[4];
                ldm_x4(b, qB + qOff + (uint32_t)np*16u*RSB + (uint32_t)k0*2u);
                mma_bf16(acc[0][2*np+0], a0, b[0], b[1]);
                mma_bf16(acc[0][2*np+1], a0, b[2], b[3]);
                mma_bf16(acc[1][2*np+0], a1, b[0], b[1]);
                mma_bf16(acc[1][2*np+1], a1, b[2], b[3]);
            }
        }

        #pragma unroll
        for (int mt = 0; mt < 2; mt++) {
            #pragma unroll
            for (int rh = 0; rh < 2; rh++) {
                int s = mt*2 + rh;
                float v[16];
                float vm = -INFINITY;
                #pragma unroll
                for (int nt = 0; nt < 8; nt++) {
                    v[2*nt+0] = acc[mt][nt][rh*2+0] * scale;
                    v[2*nt+1] = acc[mt][nt][rh*2+1] * scale;
                    vm = fmaxf(vm, fmaxf(v[2*nt], v[2*nt+1]));
                }
                vm = fmaxf(vm, __shfl_xor_sync(0xffffffffu, vm, 1));
                vm = fmaxf(vm, __shfl_xor_sync(0xffffffffu, vm, 2));
                float mn = fmaxf(mrun[s], vm);
                float es = 0.0f;
                #pragma unroll
                for (int i = 0; i < 16; i++) es += __expf(v[i] - mn);
                es += __shfl_xor_sync(0xffffffffu, es, 1);
                es += __shfl_xor_sync(0xffffffffu, es, 2);
                srun[s] = srun[s] * __expf(mrun[s] - mn) + es;
                mrun[s] = mn;
            }
        }
    }

    if ((lane & 3) == 0) {
        int gid = lane >> 2;
        int slot = blockIdx.y*2 + ng;
        #pragma unroll
        for (int mt = 0; mt < 2; mt++) {
            #pragma unroll
            for (int rh = 0; rh < 2; rh++) {
                int s = mt*2 + rh;
                int row = m0 + mg*32 + mt*16 + rh*8 + gid;
                pm[row*ppart + slot] = mrun[s];
                ps[row*ppart + slot] = srun[s];
            }
        }
    }
}

// ------------------------- gumbel-softmax (soft, in-place) + hard argmax -------------------------
__global__ void k_softmax_gumbel(float* __restrict__ Lm, const float* __restrict__ uS,
                                 const float* __restrict__ uH, float* __restrict__ assignOut) {
    int b = blockIdx.x, t = threadIdx.x;
    __shared__ float sh[8];
    __shared__ float shv[8];
    __shared__ int shi[8];
    float4* L4 = reinterpret_cast<float4*>(Lm) + b*(CK/4);
    float4 l = L4[t];
    float4 us = (reinterpret_cast<const float4*>(uS) + b*(CK/4))[t];
    float4 uh = (reinterpret_cast<const float4*>(uH) + b*(CK/4))[t];
    float zs[4] = { (l.x + gumbelf(us.x))*2.0f, (l.y + gumbelf(us.y))*2.0f,
                    (l.z + gumbelf(us.z))*2.0f, (l.w + gumbelf(us.w))*2.0f };
    float zh[4] = { l.x + gumbelf(uh.x), l.y + gumbelf(uh.y),
                    l.z + gumbelf(uh.z), l.w + gumbelf(uh.w) };
    float vm = fmaxf(fmaxf(zs[0], zs[1]), fmaxf(zs[2], zs[3]));
    #pragma unroll
    for (int o = 16; o; o >>= 1) vm = fmaxf(vm, __shfl_xor_sync(0xffffffffu, vm, o));
    if ((t & 31) == 0) sh[t >> 5] = vm;
    __syncthreads();
    float bm = sh[0];
    #pragma unroll
    for (int i = 1; i < 8; i++) bm = fmaxf(bm, sh[i]);
    float e[4];
    float es = 0.0f;
    #pragma unroll
    for (int j = 0; j < 4; j++) { e[j] = __expf(zs[j] - bm); es += e[j]; }
    #pragma unroll
    for (int o = 16; o; o >>= 1) es += __shfl_xor_sync(0xffffffffu, es, o);
    __syncthreads();
    if ((t & 31) == 0) sh[t >> 5] = es;
    __syncthreads();
    float S = 0.0f;
    #pragma unroll
    for (int i = 0; i < 8; i++) S += sh[i];
    float inv = 1.0f / S;
    L4[t] = make_float4(e[0]*inv, e[1]*inv, e[2]*inv, e[3]*inv);
    float bv = zh[0]; int bi = t*4;
    #pragma unroll
    for (int j = 1; j < 4; j++) if (zh[j] > bv) { bv = zh[j]; bi = t*4 + j; }
    #pragma unroll
    for (int o = 16; o; o >>= 1) {
        float ov = __shfl_xor_sync(0xffffffffu, bv, o);
        int   oi = __shfl_xor_sync(0xffffffffu, bi, o);
        if (ov > bv || (ov == bv && oi < bi)) { bv = ov; bi = oi; }
    }
    if ((t & 31) == 0) { shv[t >> 5] = bv; shi[t >> 5] = bi; }
    __syncthreads();
    if (t == 0 && assignOut) {
        float fbv = shv[0]; int fbi = shi[0];
        #pragma unroll
        for (int i = 1; i < 8; i++)
            if (shv[i] > fbv || (shv[i] == fbv && shi[i] < fbi)) { fbv = shv[i]; fbi = shi[i]; }
        assignOut[b] = (float)fbi;
    }
}

// column sums of assign [CB, CK] -> norm[CK]
__global__ void k_colsum(const float* __restrict__ A, float* __restrict__ norm) {
    int col = blockIdx.x * 256 + threadIdx.x;
    float s0 = 0, s1 = 0, s2 = 0, s3 = 0;
    for (int b = 0; b < CB; b += 4) {
        s0 += A[(b+0)*CK + col];
        s1 += A[(b+1)*CK + col];
        s2 += A[(b+2)*CK + col];
        s3 += A[(b+3)*CK + col];
    }
    norm[col] = (s0 + s1) + (s2 + s3);
}

// per-row dot of two [R,256] matrices (l_pos)
__global__ void k_rowdot(const float* __restrict__ A, const float* __restrict__ Bv,
                         float* __restrict__ out) {
    int r = blockIdx.x, t = threadIdx.x;  // 32 threads
    const float4* a4 = reinterpret_cast<const float4*>(A) + r*64;
    const float4* b4 = reinterpret_cast<const float4*>(Bv) + r*64;
    float4 a = a4[t], b = b4[t];
    float s = a.x*b.x + a.y*b.y + a.z*b.z + a.w*b.w;
    a = a4[t + 32]; b = b4[t + 32];
    s += a.x*b.x + a.y*b.y + a.z*b.z + a.w*b.w;
    #pragma unroll
    for (int o = 16; o; o >>= 1) s += __shfl_xor_sync(0xffffffffu, s, o);
    if (t == 0) out[r] = s;
}

__device__ __forceinline__ float blockReduceSum1024(float v, float* sh) {
    int t = threadIdx.x;
    #pragma unroll
    for (int o = 16; o; o >>= 1) v += __shfl_xor_sync(0xffffffffu, v, o);
    if ((t & 31) == 0) sh[t >> 5] = v;
    __syncthreads();
    float s = 0.0f;
    if (t < 32) {
        s = sh[t];
        #pragma unroll
        for (int o = 16; o; o >>= 1) s += __shfl_xor_sync(0xffffffffu, s, o);
    }
    return s;
}

__global__ void k_final(const float* __restrict__ pmN, const float* __restrict__ psN,
                        const float* __restrict__ lposN,
                        const float* __restrict__ pmK, const float* __restrict__ psK,
                        const float* __restrict__ lposK,
                        float* __restrict__ outLoss, int ppN, int ppK) {
    int t = threadIdx.x;
    __shared__ float sh[32];
    float accN = 0.0f;
    for (int r = t; r < CB; r += 1024) {
        float lp = lposN[r] * INV_TEMP;
        float m = lp, s = 1.0f;
        for (int p = 0; p < ppN; p++) {
            float mp = pmN[r*ppN + p], sp = psN[r*ppN + p];
            float mn = fmaxf(m, mp);
            s = s * __expf(m - mn) + sp * __expf(mp - mn);
            m = mn;
        }
        accN += m + logf(s) - lp;
    }
    float sumN = blockReduceSum1024(accN, sh);
    __syncthreads();
    float accK = 0.0f;
    {
        int r = t;
        float lp = lposK[r] * INV_TEMP;
        float m = lp, s = 1.0f;
        for (int p = 0; p < ppK; p++) {
            float mp = pmK[r*ppK + p], sp = psK[r*ppK + p];
            float mn = fmaxf(m, mp);
            s = s * __expf(m - mn) + sp * __expf(mp - mn);
            m = mn;
        }
        accK = m + logf(s) - lp;
    }
    float sumK = blockReduceSum1024(accK, sh);
    if (t == 0) *outLoss = sumN / (float)CB + sumK / (float)CK;
}

// ------------------------- host launcher (multi-stream graph fork/join) -------------------------
extern "C" void kernel_launch(void* const* d_in, const int* in_sizes, int n_in,
                              void* d_out, int out_size) {
    const float* x1       = (const float*)d_in[0];
    const float* x2       = (const float*)d_in[1];
    const float* W1       = (const float*)d_in[2];
    const float* W2       = (const float*)d_in[3];
    const float* context1 = (const float*)d_in[4];
    const float* context2 = (const float*)d_in[5];
    const float* queue_n  = (const float*)d_in[6];
    const float* queue_k  = (const float*)d_in[7];
    const float* u1a      = (const float*)d_in[8];
    const float* u1b      = (const float*)d_in[9];
    const float* u2a      = (const float*)d_in[10];
    const float* u2b      = (const float*)d_in[11];
    const float* qnoise   = (const float*)d_in[12];

    float* out       = (float*)d_out;
    float* outAssign = out;
    float* outF2     = out + CB;
    float* outAggk2  = outF2 + (size_t)CB*CD;
    float* outLoss   = outAggk2 + (size_t)CK*CD;

    float *pF1, *pL, *pL2, *pAggk1, *pCpart,
          *pNorm1, *pNorm2, *pLposN, *pLposK, *pPmN, *pPsN, *pPmK, *pPsK;
    __nv_bfloat16 *pXh, *pXl, *pX2h, *pX2l, *pWth, *pWtl, *pWt2h, *pWt2l,
                  *pF1h, *pF1l, *pF2h, *pF2l,
                  *pCtx1h, *pCtx1l, *pCtx2h, *pCtx2l,
                  *pLTh, *pLTl, *pLT2h, *pLT2l, *pFTh, *pFTl, *pFT2h, *pFT2l,
                  *pAggk1b, *pQnb, *pQkb;
    cudaGetSymbolAddress((void**)&pF1,     g_F1);
    cudaGetSymbolAddress((void**)&pL,      g_L);
    cudaGetSymbolAddress((void**)&pL2,     g_L2);
    cudaGetSymbolAddress((void**)&pAggk1,  g_aggk1);
    cudaGetSymbolAddress((void**)&pCpart,  g_Cpart);
    cudaGetSymbolAddress((void**)&pNorm1,  g_norm1);
    cudaGetSymbolAddress((void**)&pNorm2,  g_norm2);
    cudaGetSymbolAddress((void**)&pLposN,  g_lposN);
    cudaGetSymbolAddress((void**)&pLposK,  g_lposK);
    cudaGetSymbolAddress((void**)&pPmN,    g_pmN);
    cudaGetSymbolAddress((void**)&pPsN,    g_psN);
    cudaGetSymbolAddress((void**)&pPmK,    g_pmK);
    cudaGetSymbolAddress((void**)&pPsK,    g_psK);
    cudaGetSymbolAddress((void**)&pXh,     g_xh);
    cudaGetSymbolAddress((void**)&pXl,     g_xl);
    cudaGetSymbolAddress((void**)&pX2h,    g_x2h);
    cudaGetSymbolAddress((void**)&pX2l,    g_x2l);
    cudaGetSymbolAddress((void**)&pWth,    g_wth);
    cudaGetSymbolAddress((void**)&pWtl,    g_wtl);
    cudaGetSymbolAddress((void**)&pWt2h,   g_wt2h);
    cudaGetSymbolAddress((void**)&pWt2l,   g_wt2l);
    cudaGetSymbolAddress((void**)&pF1h,    g_F1h);
    cudaGetSymbolAddress((void**)&pF1l,    g_F1l);
    cudaGetSymbolAddress((void**)&pF2h,    g_F2h);
    cudaGetSymbolAddress((void**)&pF2l,    g_F2l);
    cudaGetSymbolAddress((void**)&pCtx1h,  g_ctx1h);
    cudaGetSymbolAddress((void**)&pCtx1l,  g_ctx1l);
    cudaGetSymbolAddress((void**)&pCtx2h,  g_ctx2h);
    cudaGetSymbolAddress((void**)&pCtx2l,  g_ctx2l);
    cudaGetSymbolAddress((void**)&pLTh,    g_LTh);
    cudaGetSymbolAddress((void**)&pLTl,    g_LTl);
    cudaGetSymbolAddress((void**)&pLT2h,   g_LT2h);
    cudaGetSymbolAddress((void**)&pLT2l,   g_LT2l);
    cudaGetSymbolAddress((void**)&pFTh,    g_FTh);
    cudaGetSymbolAddress((void**)&pFTl,    g_FTl);
    cudaGetSymbolAddress((void**)&pFT2h,   g_FT2h);
    cudaGetSymbolAddress((void**)&pFT2l,   g_FT2l);
    cudaGetSymbolAddress((void**)&pAggk1b, g_aggk1b);
    cudaGetSymbolAddress((void**)&pQnb,    g_qnb);
    cudaGetSymbolAddress((void**)&pQkb,    g_qkb);

    // streams/events created once (host-side resources only; identical work every call)
    static cudaStream_t sB = 0, sQ = 0, sN = 0;
    static cudaEvent_t eRoot, eF1, eF2, eQn, eQk, eAgg2, eN;
    static bool inited = false;
    if (!inited) {
        cudaStreamCreateWithFlags(&sB, cudaStreamNonBlocking);
        cudaStreamCreateWithFlags(&sQ, cudaStreamNonBlocking);
        cudaStreamCreateWithFlags(&sN, cudaStreamNonBlocking);
        cudaEventCreateWithFlags(&eRoot, cudaEventDisableTiming);
        cudaEventCreateWithFlags(&eF1,   cudaEventDisableTiming);
        cudaEventCreateWithFlags(&eF2,   cudaEventDisableTiming);
        cudaEventCreateWithFlags(&eQn,   cudaEventDisableTiming);
        cudaEventCreateWithFlags(&eQk,   cudaEventDisableTiming);
        cudaEventCreateWithFlags(&eAgg2, cudaEventDisableTiming);
        cudaEventCreateWithFlags(&eN,    cudaEventDisableTiming);
        cudaFuncSetAttribute(k_lse_mma, cudaFuncAttributeMaxDynamicSharedMemorySize, LSE_SMEM);
        cudaFuncSetAttribute(k_mma3, cudaFuncAttributeMaxDynamicSharedMemorySize, GT_SMEM);
        inited = true;
    }

    dim3 t328(32, 8);
    const int MN4_FEAT = CB*CD/4;   // float4 stride of feature partials
    const int MN4_AGG  = CK*CD/4;
    float* cpFeat1 = pCpart;                       // 2 x CB*CD
    float* cpFeat2 = pCpart + (size_t)2*CB*CD;     // 2 x CB*CD
    float* cpAgg1  = pCpart + (size_t)4*CB*CD;     // 8 x CK*CD
    float* cpAgg2  = pCpart + (size_t)6*CB*CD;     // 8 x CK*CD

    // ---- fork ----
    cudaEventRecord(eRoot, 0);
    cudaStreamWaitEvent(sB, eRoot, 0);
    cudaStreamWaitEvent(sQ, eRoot, 0);

    // ---- sQ: queue prep ----
    k_l2norm<<<CL, 64, 0, sQ>>>(queue_n, 1, 0, nullptr, pQnb, nullptr, nullptr);
    cudaEventRecord(eQn, sQ);
    k_queue_combine<<<CKQ, 64, 0, sQ>>>(queue_k, qnoise, pQkb);
    cudaEventRecord(eQk, sQ);

    // ---- main (stream 0): view 1 ----
    k_l2norm<<<CK, 64>>>(context1, 1, 0, nullptr, pCtx1h, pCtx1l, nullptr);
    k_tsplit<<<dim3(CD/32, CDIN/32), t328>>>(W1, pWth, pWtl, CDIN, CD);
    k_split<<<CB*CDIN/4/256, 256>>>(x1, pXh, pXl);
    k_mma3<<<dim3(CB/128, CD/128, 2), 256, GT_SMEM>>>(pXh, pXl, pWth, pWtl, cpFeat1, CB, CD, CDIN, 2);
    k_l2norm<<<CB, 64>>>(cpFeat1, 2, MN4_FEAT, pF1, pF1h, pF1l, nullptr);
    cudaEventRecord(eF1, 0);

    // ---- sN: big LSE over queue_n (needs F1h + qnb) ----
    cudaStreamWaitEvent(sN, eF1, 0);
    cudaStreamWaitEvent(sN, eQn, 0);
    k_lse_mma<<<dim3(CB/128, PS_N), 256, LSE_SMEM, sN>>>(pF1h, pQnb, pPmN, pPsN, CL/PS_N, PP_N, INV_TEMP);
    cudaEventRecord(eN, sN);

    // ---- sB: view 2 full chain ----
    k_l2norm<<<CK, 64, 0, sB>>>(context2, 1, 0, nullptr, pCtx2h, pCtx2l, nullptr);
    k_tsplit<<<dim3(CD/32, CDIN/32), t328, 0, sB>>>(W2, pWt2h, pWt2l, CDIN, CD);
    k_split<<<CB*CDIN/4/256, 256, 0, sB>>>(x2, pX2h, pX2l);
    k_mma3<<<dim3(CB/128, CD/128, 2), 256, GT_SMEM, sB>>>(pX2h, pX2l, pWt2h, pWt2l, cpFeat2, CB, CD, CDIN, 2);
    k_l2norm<<<CB, 64, 0, sB>>>(cpFeat2, 2, MN4_FEAT, outF2, pF2h, pF2l, nullptr);
    cudaEventRecord(eF2, sB);
    k_mma3<<<dim3(CB/128, CK/128, 1), 256, GT_SMEM, sB>>>(pF2h, pF2l, pCtx2h, pCtx2l, pL2, CB, CK, CD, 1);
    k_softmax_gumbel<<<CB, 256, 0, sB>>>(pL2, u2a, u2b, nullptr);
    k_colsum<<<CK/256, 256, 0, sB>>>(pL2, pNorm2);
    k_tsplit<<<dim3(CK/32, CB/32), t328, 0, sB>>>(pL2, pLT2h, pLT2l, CB, CK);
    k_tsplit<<<dim3(CD/32, CB/32), t328, 0, sB>>>(outF2, pFT2h, pFT2l, CB, CD);
    k_mma3<<<dim3(CK/128, CD/128, 8), 256, GT_SMEM, sB>>>(pLT2h, pLT2l, pFT2h, pFT2l, cpAgg2, CK, CD, CB, 8);
    k_l2norm<<<CK, 64, 0, sB>>>(cpAgg2, 8, MN4_AGG, outAggk2, nullptr, nullptr, pNorm2);
    cudaEventRecord(eAgg2, sB);

    // ---- main: view 1 continues ----
    k_mma3<<<dim3(CB/128, CK/128, 1), 256, GT_SMEM>>>(pF1h, pF1l, pCtx1h, pCtx1l, pL, CB, CK, CD, 1);
    k_softmax_gumbel<<<CB, 256>>>(pL, u1a, u1b, outAssign);
    k_colsum<<<CK/256, 256>>>(pL, pNorm1);
    k_tsplit<<<dim3(CK/32, CB/32), t328>>>(pL, pLTh, pLTl, CB, CK);
    k_tsplit<<<dim3(CD/32, CB/32), t328>>>(pF1, pFTh, pFTl, CB, CD);
    k_mma3<<<dim3(CK/128, CD/128, 8), 256, GT_SMEM>>>(pLTh, pLTl, pFTh, pFTl, cpAgg1, CK, CD, CB, 8);
    k_l2norm<<<CK, 64>>>(cpAgg1, 8, MN4_AGG, pAggk1, pAggk1b, nullptr, pNorm1);

    // ---- main: LSE over queue_k, positives, join, final ----
    cudaStreamWaitEvent(0, eQk, 0);
    k_lse_mma<<<dim3(CK/128, PS_K), 256, LSE_SMEM>>>(pAggk1b, pQkb, pPmK, pPsK, CKQ/PS_K, PP_K, INV_TEMP);
    cudaStreamWaitEvent(0, eF2, 0);
    k_rowdot<<<CB, 32>>>(pF1, outF2, pLposN);
    cudaStreamWaitEvent(0, eAgg2, 0);
    k_rowdot<<<CK, 32>>>(pAggk1, outAggk2, pLposK);
    cudaStreamWaitEvent(0, eN, 0);
    k_final<<<1, 1024>>>(pPmN, pPsN, pLposN, pPmK, pPsK, pLposK, outLoss, PP_N, PP_K);
}